// round 11
// baseline (speedup 1.0000x reference)
#include <cuda_runtime.h>
#include <math.h>

#define NROWS 524288
#define H 128
#define NSEG 129          // max segments (128 layer-1 breakpoints + 1)
#define NB (NSEG + 1)     // boundary entries B[0..129]
#define TPB 256
#define ROWS_PER_BLOCK 8192
#define GRIDX (NROWS / ROWS_PER_BLOCK)   // 64

// level_data is a module-level constant of the problem:
//   [GRID_SIZE=100, N_GREEN=524288, N_RED=524288]; scale = 100^2-1 = 9999.
#define LD0 100.0f
#define LD1 524288.0f
#define LD2 524288.0f
#define SCALE_CONST 9999.0f
#define NEG_CUT -18.0f    // for x <= -18: __expf(x)-1 rounds to -1.0f exactly

// Epilogue: sigmoid((o+b3)/500) * 9999, truncate, as float
__device__ __forceinline__ float coord_of(float o, float b3) {
    float t = (o + b3) * (1.0f / 500.0f);
    float sg = 1.0f / (1.0f + __expf(-t));
    return (float)(int)(sg * SCALE_CONST);
}

// Branchless ELU, exact vs reference within fp32 rounding for all x
__device__ __forceinline__ float elu_fast(float x) {
    float ex = __expf(fminf(x, 0.0f)) - 1.0f;
    return (x >= 0.0f) ? x : ex;
}

// ---------------------------------------------------------------------------
// Fused kernel: grid (GRIDX, 2), 256 threads. Each block owns 8192 rows of
// one MLP and is fully self-contained:
//   1) layer-1 affine coeffs (threads 0..127, one unit each)
//   2) breakpoint rank-sort -> shared boundary list
//   3) per overlapping segment: pair-split 128x128 GEMV -> (c0,c1) per unit,
//      regime classification, fold linear/saturated units into (A0,A1),
//      compact active units to shared, constant-fill detection
//   4) sync-free strided row loop (fill store or tiny active-list compute)
// ---------------------------------------------------------------------------
__global__ void __launch_bounds__(TPB) fused_kernel(
    const float* __restrict__ z,
    const float* __restrict__ gW1, const float* __restrict__ gb1,
    const float* __restrict__ gW2, const float* __restrict__ gb2,
    const float* __restrict__ gW3, const float* __restrict__ gb3,
    const float* __restrict__ rW1, const float* __restrict__ rb1,
    const float* __restrict__ rW2, const float* __restrict__ rb2,
    const float* __restrict__ rW3, const float* __restrict__ rb3,
    float* __restrict__ out)
{
    __shared__ float s_zext[16];
    __shared__ float s_sb[H], s_sw[H];
    __shared__ int   s_bk[H];
    __shared__ int   s_B[NB];
    __shared__ float s_ac0[H], s_ac1[H], s_awk[H];
    __shared__ float s_wA0[8], s_wA1[8];
    __shared__ int   s_wn[8];
    __shared__ float s_A0, s_A1, s_fill;
    __shared__ int   s_nact, s_isfill;

    const int t    = threadIdx.x;
    const int lane = t & 31;
    const int wid  = t >> 5;
    const int mlp  = blockIdx.y;

    const float* W1 = mlp ? rW1 : gW1;
    const float* b1 = mlp ? rb1 : gb1;
    const float* W2 = mlp ? rW2 : gW2;
    const float* b2 = mlp ? rb2 : gb2;
    const float* W3 = mlp ? rW3 : gW3;
    const float  b3 = (mlp ? rb3 : gb3)[0];

    if (t < 10) s_zext[t] = z[t];
    if (t == 10) s_zext[10] = LD0;
    if (t == 11) s_zext[11] = LD1;
    if (t == 12) s_zext[12] = LD2;
    __syncthreads();

    // --- Layer-1 affine coefficients + breakpoints (threads 0..127) ---
    float base = 0.0f, w = 0.0f;
    if (t < H) {
        base = b1[t];
#pragma unroll
        for (int j = 0; j < 13; ++j) base = fmaf(W1[t * 14 + j], s_zext[j], base);
        w = W1[t * 14 + 13];

        int bk = NROWS;
        if (w != 0.0f) {
            float tt = -base / w;
            if (tt > 0.0f && tt < (float)NROWS) {
                bk = (int)ceilf(tt);
                if (bk < 1) bk = 1;
                if (bk > NROWS) bk = NROWS;
            }
        }
        s_bk[t] = bk;
    }
    __syncthreads();

    if (t < H) {
        int bk = s_bk[t];
        int r = 0;
#pragma unroll 8
        for (int j = 0; j < H; ++j) {
            int v = s_bk[j];
            r += (v < bk) || (v == bk && j < t);
        }
        if (t == 0) { s_B[0] = 0; s_B[NB - 1] = NROWS; }
        s_B[1 + r] = bk;
    }
    __syncthreads();

    // --- This block's row range + starting segment (binary search) ---
    const int r0   = blockIdx.x * ROWS_PER_BLOCK;
    const int rend = r0 + ROWS_PER_BLOCK;
    float* outp = out + mlp * NROWS;

    int lo = 0, hi = NSEG - 1;
    while (lo < hi) {
        int mid = (lo + hi + 1) >> 1;
        if (s_B[mid] <= r0) lo = mid; else hi = mid - 1;
    }
    int cur = lo;

    // Pair-split GEMV setup: thread pair (2k, 2k+1) handles unit k = t>>1,
    // half h = t&1 (j in [h*64, h*64+64)).
    const int k2 = t >> 1, hh = t & 1;
    const float myb2 = b2[k2];
    const float mywk = W3[k2];
    const float4* W2v = (const float4*)(W2 + k2 * H + hh * 64);

    int segS = r0;
    while (segS < rend) {
        while (cur < NSEG - 1 && s_B[cur + 1] <= segS) ++cur;
        int segE = min(s_B[cur + 1], rend);
        if (segE <= segS) segE = rend;                 // safety
        const int a = segS, bnd = segE;

        __syncthreads();           // previous iteration's smem reads done
        if (t < H) {
            // leaky slope constant within the segment; probe i = a
            float pre = fmaf((float)a, w, base);
            float sl  = (pre >= 0.0f) ? 1.0f : 0.2f;
            s_sb[t] = sl * base;
            s_sw[t] = sl * w;
        }
        __syncthreads();

        // --- GEMV halves: c0/c1 for unit k2 over this segment ---
        float p0 = hh ? 0.0f : myb2;
        float p1 = 0.0f;
#pragma unroll
        for (int jv = 0; jv < 16; ++jv) {
            float4 wv = __ldg(&W2v[jv]);
            int j = hh * 64 + jv * 4;
            p0 = fmaf(wv.x, s_sb[j + 0], p0);  p1 = fmaf(wv.x, s_sw[j + 0], p1);
            p0 = fmaf(wv.y, s_sb[j + 1], p0);  p1 = fmaf(wv.y, s_sw[j + 1], p1);
            p0 = fmaf(wv.z, s_sb[j + 2], p0);  p1 = fmaf(wv.z, s_sw[j + 2], p1);
            p0 = fmaf(wv.w, s_sb[j + 3], p0);  p1 = fmaf(wv.w, s_sw[j + 3], p1);
        }
        // fp add is commutative -> both pair threads get the identical value
        float c0 = p0 + __shfl_xor_sync(0xFFFFFFFFu, p0, 1);
        float c1 = p1 + __shfl_xor_sync(0xFFFFFFFFu, p1, 1);

        // --- Classification over rows [a, bnd-1] (x monotone in i) ---
        float xa = fmaf((float)a, c1, c0);
        float xb = fmaf((float)(bnd - 1), c1, c0);
        float xlo = fminf(xa, xb), xhi = fmaxf(xa, xb);
        bool lin = (xlo >= 0.0f);
        bool neg = (xhi <= NEG_CUT);
        int active = (!lin && !neg && hh == 0) ? 1 : 0;   // even thread records

        float cA0 = 0.0f, cA1 = 0.0f;
        if (hh == 0) {             // count each unit once
            cA0 = lin ? mywk * c0 : (neg ? -mywk : 0.0f);
            cA1 = lin ? mywk * c1 : 0.0f;
        }

        // Warp reductions (deterministic)
        float rA0 = cA0, rA1 = cA1;
#pragma unroll
        for (int off = 16; off; off >>= 1) {
            rA0 += __shfl_down_sync(0xFFFFFFFFu, rA0, off);
            rA1 += __shfl_down_sync(0xFFFFFFFFu, rA1, off);
        }
        unsigned bal = __ballot_sync(0xFFFFFFFFu, active);
        if (lane == 0) {
            s_wA0[wid] = rA0;
            s_wA1[wid] = rA1;
            s_wn[wid]  = __popc(bal);
        }
        __syncthreads();

        // Totals (fixed order; identical on every thread)
        float A0 = ((s_wA0[0] + s_wA0[1]) + (s_wA0[2] + s_wA0[3]))
                 + ((s_wA0[4] + s_wA0[5]) + (s_wA0[6] + s_wA0[7]));
        float A1 = ((s_wA1[0] + s_wA1[1]) + (s_wA1[2] + s_wA1[3]))
                 + ((s_wA1[4] + s_wA1[5]) + (s_wA1[6] + s_wA1[7]));
        int nbefore = 0, ntot = 0;
#pragma unroll
        for (int q = 0; q < 8; ++q) {
            nbefore += (q < wid) ? s_wn[q] : 0;
            ntot += s_wn[q];
        }

        if (active) {
            int idx = nbefore + __popc(bal & ((1u << lane) - 1u));
            s_ac0[idx] = c0;
            s_ac1[idx] = c1;
            s_awk[idx] = mywk;
        }
        if (t == 0) {
            // Constant-fill: affine o(i), monotone through identical epilogue
            int isf = 0; float fv = 0.0f;
            if (ntot == 0) {
                float oa = fmaf((float)a, A1, A0);
                float ob = fmaf((float)(bnd - 1), A1, A0);
                float ca = coord_of(oa, b3);
                float cb = coord_of(ob, b3);
                if (ca == cb) { isf = 1; fv = ca; }
            }
            s_isfill = isf; s_fill = fv;
            s_nact = ntot; s_A0 = A0; s_A1 = A1;
        }
        __syncthreads();

        // --- Row loop: strided, sync-free, always in-segment ---
        if (s_isfill) {
            const float fv = s_fill;
            for (int ii = a + t; ii < bnd; ii += TPB) outp[ii] = fv;
        } else {
            const float A0r = s_A0, A1r = s_A1;
            const int nact = s_nact;           // block-uniform
            for (int ii = a + t; ii < bnd; ii += TPB) {
                const float fi = (float)ii;
                float o = fmaf(fi, A1r, A0r);
                for (int j = 0; j < nact; ++j) {
                    float x = fmaf(fi, s_ac1[j], s_ac0[j]);
                    o = fmaf(s_awk[j], elu_fast(x), o);
                }
                outp[ii] = coord_of(o, b3);
            }
        }
        segS = segE;
    }
}

// ---------------------------------------------------------------------------
// Host: size-signature input scan (elements, then bytes, then positional).
// ---------------------------------------------------------------------------
struct InMap {
    int z, gW1, gb1, gW2, gb2, gW3, gb3, rW1, rb1, rW2, rb2, rW3, rb3;
    bool ok;
};

static InMap scan_sizes(const int* in_sizes, int n_in, int unit)
{
    InMap m; m.ok = false;
    int i1792[2], n1792 = 0;
    int i16384[2], n16384 = 0;
    int i128[6], n128 = 0;
    int i1[2], n1 = 0;
    int iz = -1;

    const int S_W1 = 1792 * unit, S_W2 = 16384 * unit, S_128 = 128 * unit,
              S_1 = 1 * unit, S_Z = 10 * unit;

    for (int i = 0; i < n_in; ++i) {
        int s = in_sizes[i];
        if (s == S_W1 && n1792 < 2)        i1792[n1792++] = i;
        else if (s == S_W2 && n16384 < 2)  i16384[n16384++] = i;
        else if (s == S_128 && n128 < 6)   i128[n128++] = i;
        else if (s == S_1 && n1 < 2)       i1[n1++] = i;
        else if (s == S_Z && iz < 0)       iz = i;
    }
    if (n1792 != 2 || n16384 != 2 || n128 != 6 || n1 != 2 || iz < 0) return m;

    bool dict_order = i128[0] < i16384[0];

    m.z = iz;
    m.gW1 = i1792[0];  m.rW1 = i1792[1];
    m.gW2 = i16384[0]; m.rW2 = i16384[1];
    m.gb3 = i1[0];     m.rb3 = i1[1];
    if (dict_order) {
        m.gb1 = i128[0]; m.gb2 = i128[1]; m.gW3 = i128[2];
        m.rb1 = i128[3]; m.rb2 = i128[4]; m.rW3 = i128[5];
    } else {
        m.gW3 = i128[0]; m.gb1 = i128[1]; m.gb2 = i128[2];
        m.rW3 = i128[3]; m.rb1 = i128[4]; m.rb2 = i128[5];
    }
    m.ok = true;
    return m;
}

extern "C" void kernel_launch(void* const* d_in, const int* in_sizes, int n_in,
                              void* d_out, int out_size)
{
    InMap m = scan_sizes(in_sizes, n_in, 1);
    if (!m.ok) m = scan_sizes(in_sizes, n_in, 4);
    if (!m.ok) {
        m.z = 0;
        m.gW1 = 2;  m.gb1 = 3;  m.gW2 = 4;  m.gb2 = 5;  m.gW3 = 6;  m.gb3 = 7;
        m.rW1 = 8;  m.rb1 = 9;  m.rW2 = 10; m.rb2 = 11; m.rW3 = 12; m.rb3 = 13;
    }

    const float* z   = (const float*)d_in[m.z];
    const float* gW1 = (const float*)d_in[m.gW1];
    const float* gb1 = (const float*)d_in[m.gb1];
    const float* gW2 = (const float*)d_in[m.gW2];
    const float* gb2 = (const float*)d_in[m.gb2];
    const float* gW3 = (const float*)d_in[m.gW3];
    const float* gb3 = (const float*)d_in[m.gb3];
    const float* rW1 = (const float*)d_in[m.rW1];
    const float* rb1 = (const float*)d_in[m.rb1];
    const float* rW2 = (const float*)d_in[m.rW2];
    const float* rb2 = (const float*)d_in[m.rb2];
    const float* rW3 = (const float*)d_in[m.rW3];
    const float* rb3 = (const float*)d_in[m.rb3];

    float* out = (float*)d_out;
    int nmlp = (out_size >= 2 * NROWS) ? 2 : 1;

    fused_kernel<<<dim3(GRIDX, nmlp), TPB>>>(
        z, gW1, gb1, gW2, gb2, gW3, gb3,
        rW1, rb1, rW2, rb2, rW3, rb3, out);
}

// round 12
// speedup vs baseline: 1.2619x; 1.2619x over previous
#include <cuda_runtime.h>
#include <math.h>

#define NROWS 524288
#define H 128
#define NSEG 129          // max segments (128 layer-1 breakpoints + 1)
#define NB (NSEG + 1)     // boundary entries B[0..129]
#define TPB 256
#define CHUNK 1024
#define MAXW 768          // >= NROWS/CHUNK + NSEG = 641

// level_data is a module-level constant of the problem:
//   [GRID_SIZE=100, N_GREEN=524288, N_RED=524288]; scale = 100^2-1 = 9999.
#define LD0 100.0f
#define LD1 524288.0f
#define LD2 524288.0f
#define SCALE_CONST 9999.0f
#define NEG_CUT -18.0f    // for x <= -18: __expf(x)-1 rounds to -1.0f exactly

// Per-MLP global scratch (no allocations allowed)
__device__ float4 g_hdr[2][NSEG];        // {A0, A1, fill, bits(nact|isfill<<16)}
__device__ float  g_ac0[2][NSEG][H];     // active-unit coefficients (compact)
__device__ float  g_ac1[2][NSEG][H];
__device__ float  g_awk[2][NSEG][H];
__device__ int    g_B[2][NB];            // segment boundaries
__device__ int2   g_work[2][MAXW];       // flat work list: {segment, row start}
__device__ int    g_nwork[2];

// Epilogue — identical instruction sequence in prep & main
__device__ __forceinline__ float coord_of(float o, float b3) {
    float t = (o + b3) * (1.0f / 500.0f);
    float sg = 1.0f / (1.0f + __expf(-t));
    return (float)(int)(sg * SCALE_CONST);
}

// Branchless ELU, exact vs reference within fp32 rounding for all x
__device__ __forceinline__ float elu_fast(float x) {
    float ex = __expf(fminf(x, 0.0f)) - 1.0f;
    return (x >= 0.0f) ? x : ex;
}

// ---------------------------------------------------------------------------
// Prep kernel: grid (NSEG, 2), 128 threads — one segment per block.
// Also builds the flat chunked work list via an in-block prefix scan.
// ---------------------------------------------------------------------------
__global__ void __launch_bounds__(H) prep_kernel(
    const float* __restrict__ z,
    const float* __restrict__ gW1, const float* __restrict__ gb1,
    const float* __restrict__ gW2, const float* __restrict__ gb2,
    const float* __restrict__ gW3, const float* __restrict__ gb3,
    const float* __restrict__ rW1, const float* __restrict__ rb1,
    const float* __restrict__ rW2, const float* __restrict__ rb2,
    const float* __restrict__ rW3, const float* __restrict__ rb3)
{
    __shared__ float s_zext[16];
    __shared__ float s_sb[H], s_sw[H];
    __shared__ float s_wA0[4], s_wA1[4];
    __shared__ int   s_wn[4], s_wscan[4];
    __shared__ int   s_bk[H];
    __shared__ int   s_B[NB];
    __shared__ int   s_off[H];
    __shared__ int   s_total;

    const int k    = threadIdx.x;
    const int lane = k & 31;
    const int wid  = k >> 5;
    const int mlp  = blockIdx.y;
    const int m    = blockIdx.x;
    const float* W1 = mlp ? rW1 : gW1;
    const float* b1 = mlp ? rb1 : gb1;
    const float* W2 = mlp ? rW2 : gW2;
    const float* b2 = mlp ? rb2 : gb2;
    const float* W3 = mlp ? rW3 : gW3;
    const float  b3 = (mlp ? rb3 : gb3)[0];

    if (k < 10) s_zext[k] = z[k];
    if (k == 10) s_zext[10] = LD0;
    if (k == 11) s_zext[11] = LD1;
    if (k == 12) s_zext[12] = LD2;
    __syncthreads();

    // Layer-1 affine form: pre_k(i) = base_k + i*w_k (exact: only idx varies)
    float base = b1[k];
#pragma unroll
    for (int j = 0; j < 13; ++j) base = fmaf(W1[k * 14 + j], s_zext[j], base);
    float w = W1[k * 14 + 13];

    int bk = NROWS;
    if (w != 0.0f) {
        float t = -base / w;
        if (t > 0.0f && t < (float)NROWS) {
            bk = (int)ceilf(t);
            if (bk < 1) bk = 1;
            if (bk > NROWS) bk = NROWS;
        }
    }
    s_bk[k] = bk;
    __syncthreads();

    // Rank sort -> sorted boundary list
    int r = 0;
#pragma unroll 8
    for (int j = 0; j < H; ++j) {
        int v = s_bk[j];
        r += (v < bk) || (v == bk && j < k);
    }
    if (k == 0) { s_B[0] = 0; s_B[NB - 1] = NROWS; }
    s_B[1 + r] = bk;
    __syncthreads();

    if (m == 0) {
        for (int q = k; q < NB; q += H) g_B[mlp][q] = s_B[q];
    }

    // --- Chunk-count prefix scan over segments 0..127 (thread k = seg k) ---
    {
        int len = s_B[k + 1] - s_B[k];
        int cnt = (len > 0) ? (len + CHUNK - 1) / CHUNK : 0;
        int v = cnt;
#pragma unroll
        for (int o = 1; o < 32; o <<= 1) {
            int u = __shfl_up_sync(0xFFFFFFFFu, v, o);
            if (lane >= o) v += u;
        }
        if (lane == 31) s_wscan[wid] = v;
        __syncthreads();
        int add = 0;
#pragma unroll
        for (int q = 0; q < 4; ++q) add += (q < wid) ? s_wscan[q] : 0;
        int incl = v + add;
        s_off[k] = incl - cnt;          // exclusive offset for seg k
        if (k == H - 1) s_total = incl; // total over segs 0..127
    }
    __syncthreads();

    const int s0 = s_B[m], s1 = s_B[m + 1];

    if (m == 0 && k == 0) {
        int l128 = s_B[NSEG] - s_B[NSEG - 1];
        int c128 = (l128 > 0) ? (l128 + CHUNK - 1) / CHUNK : 0;
        g_nwork[mlp] = s_total + c128;
    }
    if (s0 >= s1) return;               // empty segment

    // Emit this segment's work items
    {
        int off = (m < H) ? s_off[m] : s_total;
        int mycnt = (s1 - s0 + CHUNK - 1) / CHUNK;
        for (int i = k; i < mycnt; i += H)
            g_work[mlp][off + i] = make_int2(m, s0 + i * CHUNK);
    }

    // leaky slope constant within the segment; probe i = s0
    {
        float pre = fmaf((float)s0, w, base);
        float sl  = (pre >= 0.0f) ? 1.0f : 0.2f;
        s_sb[k] = sl * base;
        s_sw[k] = sl * w;
    }
    __syncthreads();

    const float4* W2v = (const float4*)(W2 + k * H);
    const float wk = W3[k];
    float c0 = b2[k], c1 = 0.0f;
#pragma unroll 4
    for (int jv = 0; jv < H / 4; ++jv) {
        float4 wv = __ldg(&W2v[jv]);
        int j = jv * 4;
        c0 = fmaf(wv.x, s_sb[j + 0], c0);  c1 = fmaf(wv.x, s_sw[j + 0], c1);
        c0 = fmaf(wv.y, s_sb[j + 1], c0);  c1 = fmaf(wv.y, s_sw[j + 1], c1);
        c0 = fmaf(wv.z, s_sb[j + 2], c0);  c1 = fmaf(wv.z, s_sw[j + 2], c1);
        c0 = fmaf(wv.w, s_sb[j + 3], c0);  c1 = fmaf(wv.w, s_sw[j + 3], c1);
    }

    // Classify over i in [s0, s1-1]: x(i)=RN(c0+i*c1) is monotone in i.
    float xa = fmaf((float)s0, c1, c0);
    float xb = fmaf((float)(s1 - 1), c1, c0);
    float lo = fminf(xa, xb), hi = fmaxf(xa, xb);
    bool lin = (lo >= 0.0f);
    bool neg = (hi <= NEG_CUT);
    int active = (!lin && !neg) ? 1 : 0;

    float cA0 = lin ? wk * c0 : (neg ? -wk : 0.0f);
    float cA1 = lin ? wk * c1 : 0.0f;

    float rA0 = cA0, rA1 = cA1;
#pragma unroll
    for (int off = 16; off; off >>= 1) {
        rA0 += __shfl_down_sync(0xFFFFFFFFu, rA0, off);
        rA1 += __shfl_down_sync(0xFFFFFFFFu, rA1, off);
    }
    unsigned bal = __ballot_sync(0xFFFFFFFFu, active);
    if (lane == 0) {
        s_wA0[wid] = rA0;
        s_wA1[wid] = rA1;
        s_wn[wid]  = __popc(bal);
    }
    __syncthreads();

    float A0 = (s_wA0[0] + s_wA0[1]) + (s_wA0[2] + s_wA0[3]);
    float A1 = (s_wA1[0] + s_wA1[1]) + (s_wA1[2] + s_wA1[3]);
    int nbefore = 0;
#pragma unroll
    for (int q = 0; q < 4; ++q) nbefore += (q < wid) ? s_wn[q] : 0;
    int ntot = s_wn[0] + s_wn[1] + s_wn[2] + s_wn[3];

    if (k == 0) {
        int isf = 0; float fv = 0.0f;
        if (ntot == 0) {
            // o(i) affine -> monotone through identical epilogue; equal
            // endpoint coords => constant segment.
            float oa = fmaf((float)s0, A1, A0);
            float ob = fmaf((float)(s1 - 1), A1, A0);
            float ca = coord_of(oa, b3);
            float cb = coord_of(ob, b3);
            if (ca == cb) { isf = 1; fv = ca; }
        }
        int flags = ntot | (isf << 16);
        g_hdr[mlp][m] = make_float4(A0, A1, fv, __int_as_float(flags));
    }

    if (active) {
        int idx = nbefore + __popc(bal & ((1u << lane) - 1u));
        g_ac0[mlp][m][idx] = c0;
        g_ac1[mlp][m][idx] = c1;
        g_awk[mlp][m][idx] = wk;
    }
}

// ---------------------------------------------------------------------------
// Main kernel: grid (MAXW, 2), 256 threads. One work item (segment-chunk,
// <=1024 rows, single segment) per block. No straggler possible.
// ---------------------------------------------------------------------------
__global__ void __launch_bounds__(TPB) main_kernel(
    const float* __restrict__ gb3, const float* __restrict__ rb3,
    float* __restrict__ out)
{
    __shared__ float s_ac0[H], s_ac1[H], s_awk[H];

    const int t   = threadIdx.x;
    const int mlp = blockIdx.y;
    const int bx  = blockIdx.x;

    if (bx >= g_nwork[mlp]) return;

    const int2 it = g_work[mlp][bx];
    const int m = it.x, start = it.y;
    const int segE = g_B[mlp][m + 1];
    const int end = min(start + CHUNK, segE);

    const float4 hdr = g_hdr[mlp][m];
    const int flags  = __float_as_int(hdr.w);
    const int nact   = flags & 0xFFFF;
    const int isfill = flags >> 16;
    float* outp = out + mlp * NROWS;

    if (isfill) {
        const float fv = hdr.z;
        for (int i = start + t; i < end; i += TPB) outp[i] = fv;
        return;
    }

    const float b3 = (mlp ? rb3 : gb3)[0];
    if (t < nact) {
        s_ac0[t] = g_ac0[mlp][m][t];
        s_ac1[t] = g_ac1[mlp][m][t];
        s_awk[t] = g_awk[mlp][m][t];
    }
    __syncthreads();

    const float A0 = hdr.x, A1 = hdr.y;
    for (int i = start + t; i < end; i += TPB) {
        const float fi = (float)i;
        float o = fmaf(fi, A1, A0);
        for (int j = 0; j < nact; ++j) {        // block-uniform trip count
            float x = fmaf(fi, s_ac1[j], s_ac0[j]);
            o = fmaf(s_awk[j], elu_fast(x), o);
        }
        outp[i] = coord_of(o, b3);
    }
}

// ---------------------------------------------------------------------------
// Host: size-signature input scan (elements, then bytes, then positional).
// ---------------------------------------------------------------------------
struct InMap {
    int z, gW1, gb1, gW2, gb2, gW3, gb3, rW1, rb1, rW2, rb2, rW3, rb3;
    bool ok;
};

static InMap scan_sizes(const int* in_sizes, int n_in, int unit)
{
    InMap m; m.ok = false;
    int i1792[2], n1792 = 0;
    int i16384[2], n16384 = 0;
    int i128[6], n128 = 0;
    int i1[2], n1 = 0;
    int iz = -1;

    const int S_W1 = 1792 * unit, S_W2 = 16384 * unit, S_128 = 128 * unit,
              S_1 = 1 * unit, S_Z = 10 * unit;

    for (int i = 0; i < n_in; ++i) {
        int s = in_sizes[i];
        if (s == S_W1 && n1792 < 2)        i1792[n1792++] = i;
        else if (s == S_W2 && n16384 < 2)  i16384[n16384++] = i;
        else if (s == S_128 && n128 < 6)   i128[n128++] = i;
        else if (s == S_1 && n1 < 2)       i1[n1++] = i;
        else if (s == S_Z && iz < 0)       iz = i;
    }
    if (n1792 != 2 || n16384 != 2 || n128 != 6 || n1 != 2 || iz < 0) return m;

    bool dict_order = i128[0] < i16384[0];

    m.z = iz;
    m.gW1 = i1792[0];  m.rW1 = i1792[1];
    m.gW2 = i16384[0]; m.rW2 = i16384[1];
    m.gb3 = i1[0];     m.rb3 = i1[1];
    if (dict_order) {
        m.gb1 = i128[0]; m.gb2 = i128[1]; m.gW3 = i128[2];
        m.rb1 = i128[3]; m.rb2 = i128[4]; m.rW3 = i128[5];
    } else {
        m.gW3 = i128[0]; m.gb1 = i128[1]; m.gb2 = i128[2];
        m.rW3 = i128[3]; m.rb1 = i128[4]; m.rb2 = i128[5];
    }
    m.ok = true;
    return m;
}

extern "C" void kernel_launch(void* const* d_in, const int* in_sizes, int n_in,
                              void* d_out, int out_size)
{
    InMap m = scan_sizes(in_sizes, n_in, 1);
    if (!m.ok) m = scan_sizes(in_sizes, n_in, 4);
    if (!m.ok) {
        m.z = 0;
        m.gW1 = 2;  m.gb1 = 3;  m.gW2 = 4;  m.gb2 = 5;  m.gW3 = 6;  m.gb3 = 7;
        m.rW1 = 8;  m.rb1 = 9;  m.rW2 = 10; m.rb2 = 11; m.rW3 = 12; m.rb3 = 13;
    }

    const float* z   = (const float*)d_in[m.z];
    const float* gW1 = (const float*)d_in[m.gW1];
    const float* gb1 = (const float*)d_in[m.gb1];
    const float* gW2 = (const float*)d_in[m.gW2];
    const float* gb2 = (const float*)d_in[m.gb2];
    const float* gW3 = (const float*)d_in[m.gW3];
    const float* gb3 = (const float*)d_in[m.gb3];
    const float* rW1 = (const float*)d_in[m.rW1];
    const float* rb1 = (const float*)d_in[m.rb1];
    const float* rW2 = (const float*)d_in[m.rW2];
    const float* rb2 = (const float*)d_in[m.rb2];
    const float* rW3 = (const float*)d_in[m.rW3];
    const float* rb3 = (const float*)d_in[m.rb3];

    float* out = (float*)d_out;
    int nmlp = (out_size >= 2 * NROWS) ? 2 : 1;

    prep_kernel<<<dim3(NSEG, 2), H>>>(z, gW1, gb1, gW2, gb2, gW3, gb3,
                                      rW1, rb1, rW2, rb2, rW3, rb3);
    main_kernel<<<dim3(MAXW, nmlp), TPB>>>(gb3, rb3, out);
}

// round 13
// speedup vs baseline: 1.4332x; 1.1358x over previous
#include <cuda_runtime.h>
#include <math.h>

#define NROWS 524288
#define H 128
#define NSEG 129          // max segments (128 layer-1 breakpoints + 1)
#define NB (NSEG + 1)     // boundary entries B[0..129]
#define TPB 256
#define CHUNK 1024
#define MAXW 768          // >= NROWS/CHUNK + NSEG = 641

// level_data is a module-level constant of the problem:
//   [GRID_SIZE=100, N_GREEN=524288, N_RED=524288]; scale = 100^2-1 = 9999.
#define LD0 100.0f
#define LD1 524288.0f
#define LD2 524288.0f
#define SCALE_CONST 9999.0f
#define NEG_CUT -18.0f    // for x <= -18: __expf(x)-1 rounds to -1.0f exactly

// Per-MLP global scratch (no allocations allowed; zero-initialized)
__device__ float  g_ac0[2][NSEG][H];     // active-unit coefficients (compact)
__device__ float  g_ac1[2][NSEG][H];
__device__ float  g_awk[2][NSEG][H];
__device__ int4   g_workA[2][MAXW];      // {start, end, m|nact<<8|isf<<16, fill}
__device__ float4 g_workB[2][MAXW];      // {A0, A1, b3, 0}

// Epilogue — identical instruction sequence everywhere
__device__ __forceinline__ float coord_of(float o, float b3) {
    float t = (o + b3) * (1.0f / 500.0f);
    float sg = 1.0f / (1.0f + __expf(-t));
    return (float)(int)(sg * SCALE_CONST);
}

// Branchless ELU, exact vs reference within fp32 rounding for all x
__device__ __forceinline__ float elu_fast(float x) {
    float ex = __expf(fminf(x, 0.0f)) - 1.0f;
    return (x >= 0.0f) ? x : ex;
}

// ---------------------------------------------------------------------------
// Prep kernel: grid (NSEG, 2), 256 threads — one segment per block.
// Pair-split GEMV; emits fat 32B work records (chunked) + compact active lists.
// ---------------------------------------------------------------------------
__global__ void __launch_bounds__(TPB) prep_kernel(
    const float* __restrict__ z,
    const float* __restrict__ gW1, const float* __restrict__ gb1,
    const float* __restrict__ gW2, const float* __restrict__ gb2,
    const float* __restrict__ gW3, const float* __restrict__ gb3,
    const float* __restrict__ rW1, const float* __restrict__ rb1,
    const float* __restrict__ rW2, const float* __restrict__ rb2,
    const float* __restrict__ rW3, const float* __restrict__ rb3)
{
    __shared__ float s_zext[16];
    __shared__ float s_sb[H], s_sw[H];
    __shared__ float s_wA0[8], s_wA1[8];
    __shared__ int   s_wn[8], s_wscan[4];
    __shared__ int   s_bk[H];
    __shared__ int   s_B[NB];
    __shared__ int   s_off[H];
    __shared__ int   s_total;
    __shared__ int   s_isf;
    __shared__ float s_fv;

    const int t    = threadIdx.x;
    const int lane = t & 31;
    const int wid  = t >> 5;
    const int mlp  = blockIdx.y;
    const int m    = blockIdx.x;
    const float* W1 = mlp ? rW1 : gW1;
    const float* b1 = mlp ? rb1 : gb1;
    const float* W2 = mlp ? rW2 : gW2;
    const float* b2 = mlp ? rb2 : gb2;
    const float* W3 = mlp ? rW3 : gW3;
    const float  b3 = (mlp ? rb3 : gb3)[0];

    if (t < 10) s_zext[t] = z[t];
    if (t == 10) s_zext[10] = LD0;
    if (t == 11) s_zext[11] = LD1;
    if (t == 12) s_zext[12] = LD2;
    __syncthreads();

    // --- Layer-1 affine coefficients + breakpoints (threads 0..127) ---
    if (t < H) {
        float base = b1[t];
#pragma unroll
        for (int j = 0; j < 13; ++j) base = fmaf(W1[t * 14 + j], s_zext[j], base);
        float w = W1[t * 14 + 13];

        int bk = NROWS;
        if (w != 0.0f) {
            float tt = -base / w;
            if (tt > 0.0f && tt < (float)NROWS) {
                bk = (int)ceilf(tt);
                if (bk < 1) bk = 1;
                if (bk > NROWS) bk = NROWS;
            }
        }
        s_bk[t] = bk;
        // stash base/w for slope step (reuse s_sb/s_sw as temp)
        s_sb[t] = base;
        s_sw[t] = w;
    }
    __syncthreads();

    if (t < H) {
        int bk = s_bk[t];
        int r = 0;
#pragma unroll 8
        for (int j = 0; j < H; ++j) {
            int v = s_bk[j];
            r += (v < bk) || (v == bk && j < t);
        }
        if (t == 0) { s_B[0] = 0; s_B[NB - 1] = NROWS; }
        s_B[1 + r] = bk;
    }
    __syncthreads();

    // --- Chunk-count prefix scan over segments 0..127 (threads 0..127) ---
    {
        int cnt = 0, v = 0;
        if (t < H) {
            int len = s_B[t + 1] - s_B[t];
            cnt = (len > 0) ? (len + CHUNK - 1) / CHUNK : 0;
            v = cnt;
#pragma unroll
            for (int o = 1; o < 32; o <<= 1) {
                int u = __shfl_up_sync(0xFFFFFFFFu, v, o);
                if (lane >= o) v += u;
            }
            if (lane == 31) s_wscan[wid] = v;
        }
        __syncthreads();
        if (t < H) {
            int add = 0;
#pragma unroll
            for (int q = 0; q < 4; ++q) add += (q < wid) ? s_wscan[q] : 0;
            s_off[t] = v + add - cnt;
            if (t == H - 1) s_total = v + add;
        }
    }
    __syncthreads();

    const int s0 = s_B[m], s1 = s_B[m + 1];
    if (s0 >= s1) return;               // empty segment, nothing to emit

    // leaky slope constant within the segment; probe i = s0 (threads 0..127)
    if (t < H) {
        float base = s_sb[t], w = s_sw[t];
        float pre = fmaf((float)s0, w, base);
        float sl  = (pre >= 0.0f) ? 1.0f : 0.2f;
        s_sb[t] = sl * base;
        s_sw[t] = sl * w;
    }
    __syncthreads();

    // --- Pair-split GEMV: pair (2k,2k+1) handles unit k = t>>1 ---
    const int k2 = t >> 1, hh = t & 1;
    const float wk = W3[k2];
    const float4* W2v = (const float4*)(W2 + k2 * H + hh * 64);
    float p0 = hh ? 0.0f : b2[k2];
    float p1 = 0.0f;
#pragma unroll
    for (int jv = 0; jv < 16; ++jv) {
        float4 wv = __ldg(&W2v[jv]);
        int j = hh * 64 + jv * 4;
        p0 = fmaf(wv.x, s_sb[j + 0], p0);  p1 = fmaf(wv.x, s_sw[j + 0], p1);
        p0 = fmaf(wv.y, s_sb[j + 1], p0);  p1 = fmaf(wv.y, s_sw[j + 1], p1);
        p0 = fmaf(wv.z, s_sb[j + 2], p0);  p1 = fmaf(wv.z, s_sw[j + 2], p1);
        p0 = fmaf(wv.w, s_sb[j + 3], p0);  p1 = fmaf(wv.w, s_sw[j + 3], p1);
    }
    float c0 = p0 + __shfl_xor_sync(0xFFFFFFFFu, p0, 1);
    float c1 = p1 + __shfl_xor_sync(0xFFFFFFFFu, p1, 1);

    // --- Classification (even threads record unit k2) ---
    float xa = fmaf((float)s0, c1, c0);
    float xb = fmaf((float)(s1 - 1), c1, c0);
    float lo = fminf(xa, xb), hi = fmaxf(xa, xb);
    bool lin = (lo >= 0.0f);
    bool neg = (hi <= NEG_CUT);
    int active = (!lin && !neg && hh == 0) ? 1 : 0;

    float cA0 = 0.0f, cA1 = 0.0f;
    if (hh == 0) {
        cA0 = lin ? wk * c0 : (neg ? -wk : 0.0f);
        cA1 = lin ? wk * c1 : 0.0f;
    }

    float rA0 = cA0, rA1 = cA1;
#pragma unroll
    for (int off = 16; off; off >>= 1) {
        rA0 += __shfl_down_sync(0xFFFFFFFFu, rA0, off);
        rA1 += __shfl_down_sync(0xFFFFFFFFu, rA1, off);
    }
    unsigned bal = __ballot_sync(0xFFFFFFFFu, active);
    if (lane == 0) {
        s_wA0[wid] = rA0;
        s_wA1[wid] = rA1;
        s_wn[wid]  = __popc(bal);
    }
    __syncthreads();

    float A0 = ((s_wA0[0] + s_wA0[1]) + (s_wA0[2] + s_wA0[3]))
             + ((s_wA0[4] + s_wA0[5]) + (s_wA0[6] + s_wA0[7]));
    float A1 = ((s_wA1[0] + s_wA1[1]) + (s_wA1[2] + s_wA1[3]))
             + ((s_wA1[4] + s_wA1[5]) + (s_wA1[6] + s_wA1[7]));
    int nbefore = 0, ntot = 0;
#pragma unroll
    for (int q = 0; q < 8; ++q) {
        nbefore += (q < wid) ? s_wn[q] : 0;
        ntot += s_wn[q];
    }

    if (active) {
        int idx = nbefore + __popc(bal & ((1u << lane) - 1u));
        g_ac0[mlp][m][idx] = c0;
        g_ac1[mlp][m][idx] = c1;
        g_awk[mlp][m][idx] = wk;
    }
    if (t == 0) {
        int isf = 0; float fv = 0.0f;
        if (ntot == 0) {
            // o(i) affine -> monotone through identical epilogue; equal
            // endpoint coords => constant segment.
            float oa = fmaf((float)s0, A1, A0);
            float ob = fmaf((float)(s1 - 1), A1, A0);
            float ca = coord_of(oa, b3);
            float cb = coord_of(ob, b3);
            if (ca == cb) { isf = 1; fv = ca; }
        }
        s_isf = isf; s_fv = fv;
    }
    __syncthreads();

    // --- Emit fat work records for this segment's chunks ---
    {
        const int off = (m < H) ? s_off[m] : s_total;
        const int mycnt = (s1 - s0 + CHUNK - 1) / CHUNK;
        const int zw = m | (ntot << 8) | (s_isf << 16);
        const int fvbits = __float_as_int(s_fv);
        const float4 wB = make_float4(A0, A1, b3, 0.0f);
        for (int i = t; i < mycnt; i += TPB) {
            int cs = s0 + i * CHUNK;
            int ce = min(cs + CHUNK, s1);
            g_workA[mlp][off + i] = make_int4(cs, ce, zw, fvbits);
            g_workB[mlp][off + i] = wB;
        }
    }
}

// ---------------------------------------------------------------------------
// Main kernel: grid (MAXW, 2), 256 threads. One chunk per block; fat record.
// Reclassifies the active list against THIS chunk's row range (windows are
// narrow, so per-chunk nact is usually 0-1). Unwritten slots are all-zero ->
// decode to {start=end=0, nact=0, isf=0}: harmless no-op.
// ---------------------------------------------------------------------------
__global__ void __launch_bounds__(TPB) main_kernel(float* __restrict__ out)
{
    __shared__ float s_ac0[H], s_ac1[H], s_awk[H];
    __shared__ float s_wA0[8], s_wA1[8];
    __shared__ int   s_wn[8];

    const int t    = threadIdx.x;
    const int lane = t & 31;
    const int wid  = t >> 5;
    const int mlp  = blockIdx.y;
    const int bx   = blockIdx.x;

    const int4   wa = g_workA[mlp][bx];
    const float4 wb = g_workB[mlp][bx];
    const int start = wa.x, end = wa.y;
    const int mm    = wa.z & 0xFF;
    const int nact  = (wa.z >> 8) & 0xFF;
    const int isf   = (wa.z >> 16) & 1;
    float* outp = out + mlp * NROWS;

    if (isf) {
        const float fv = __int_as_float(wa.w);
        for (int i = start + t; i < end; i += TPB) outp[i] = fv;
        return;
    }

    // Reclassify the segment's active units against [start, end)
    float dA0 = 0.0f, dA1 = 0.0f, a0, a1, wk;
    int act = 0;
    if (t < nact) {
        a0 = g_ac0[mlp][mm][t];
        a1 = g_ac1[mlp][mm][t];
        wk = g_awk[mlp][mm][t];
        float xa = fmaf((float)start, a1, a0);
        float xb = fmaf((float)(end - 1), a1, a0);
        float lo = fminf(xa, xb), hi = fmaxf(xa, xb);
        bool lin = (lo >= 0.0f);
        bool neg = (hi <= NEG_CUT);
        act = (!lin && !neg) ? 1 : 0;
        dA0 = lin ? wk * a0 : (neg ? -wk : 0.0f);
        dA1 = lin ? wk * a1 : 0.0f;
    }

    float r0 = dA0, r1 = dA1;
#pragma unroll
    for (int off = 16; off; off >>= 1) {
        r0 += __shfl_down_sync(0xFFFFFFFFu, r0, off);
        r1 += __shfl_down_sync(0xFFFFFFFFu, r1, off);
    }
    unsigned bal = __ballot_sync(0xFFFFFFFFu, act);
    if (lane == 0) {
        s_wA0[wid] = r0;
        s_wA1[wid] = r1;
        s_wn[wid]  = __popc(bal);
    }
    __syncthreads();

    float A0 = wb.x, A1 = wb.y;                 // fixed order: base then partials
#pragma unroll
    for (int q = 0; q < 8; ++q) { A0 += s_wA0[q]; A1 += s_wA1[q]; }
    int nbefore = 0, n2 = 0;
#pragma unroll
    for (int q = 0; q < 8; ++q) {
        nbefore += (q < wid) ? s_wn[q] : 0;
        n2 += s_wn[q];
    }
    if (act) {
        int idx = nbefore + __popc(bal & ((1u << lane) - 1u));
        s_ac0[idx] = a0;
        s_ac1[idx] = a1;
        s_awk[idx] = wk;
    }
    __syncthreads();

    const float b3 = wb.z;
    for (int i = start + t; i < end; i += TPB) {
        const float fi = (float)i;
        float o = fmaf(fi, A1, A0);
        for (int j = 0; j < n2; ++j) {          // usually 0-1 iterations
            float x = fmaf(fi, s_ac1[j], s_ac0[j]);
            o = fmaf(s_awk[j], elu_fast(x), o);
        }
        outp[i] = coord_of(o, b3);
    }
}

// ---------------------------------------------------------------------------
// Host: size-signature input scan (elements, then bytes, then positional).
// ---------------------------------------------------------------------------
struct InMap {
    int z, gW1, gb1, gW2, gb2, gW3, gb3, rW1, rb1, rW2, rb2, rW3, rb3;
    bool ok;
};

static InMap scan_sizes(const int* in_sizes, int n_in, int unit)
{
    InMap m; m.ok = false;
    int i1792[2], n1792 = 0;
    int i16384[2], n16384 = 0;
    int i128[6], n128 = 0;
    int i1[2], n1 = 0;
    int iz = -1;

    const int S_W1 = 1792 * unit, S_W2 = 16384 * unit, S_128 = 128 * unit,
              S_1 = 1 * unit, S_Z = 10 * unit;

    for (int i = 0; i < n_in; ++i) {
        int s = in_sizes[i];
        if (s == S_W1 && n1792 < 2)        i1792[n1792++] = i;
        else if (s == S_W2 && n16384 < 2)  i16384[n16384++] = i;
        else if (s == S_128 && n128 < 6)   i128[n128++] = i;
        else if (s == S_1 && n1 < 2)       i1[n1++] = i;
        else if (s == S_Z && iz < 0)       iz = i;
    }
    if (n1792 != 2 || n16384 != 2 || n128 != 6 || n1 != 2 || iz < 0) return m;

    bool dict_order = i128[0] < i16384[0];

    m.z = iz;
    m.gW1 = i1792[0];  m.rW1 = i1792[1];
    m.gW2 = i16384[0]; m.rW2 = i16384[1];
    m.gb3 = i1[0];     m.rb3 = i1[1];
    if (dict_order) {
        m.gb1 = i128[0]; m.gb2 = i128[1]; m.gW3 = i128[2];
        m.rb1 = i128[3]; m.rb2 = i128[4]; m.rW3 = i128[5];
    } else {
        m.gW3 = i128[0]; m.gb1 = i128[1]; m.gb2 = i128[2];
        m.rW3 = i128[3]; m.rb1 = i128[4]; m.rb2 = i128[5];
    }
    m.ok = true;
    return m;
}

extern "C" void kernel_launch(void* const* d_in, const int* in_sizes, int n_in,
                              void* d_out, int out_size)
{
    InMap m = scan_sizes(in_sizes, n_in, 1);
    if (!m.ok) m = scan_sizes(in_sizes, n_in, 4);
    if (!m.ok) {
        m.z = 0;
        m.gW1 = 2;  m.gb1 = 3;  m.gW2 = 4;  m.gb2 = 5;  m.gW3 = 6;  m.gb3 = 7;
        m.rW1 = 8;  m.rb1 = 9;  m.rW2 = 10; m.rb2 = 11; m.rW3 = 12; m.rb3 = 13;
    }

    const float* z   = (const float*)d_in[m.z];
    const float* gW1 = (const float*)d_in[m.gW1];
    const float* gb1 = (const float*)d_in[m.gb1];
    const float* gW2 = (const float*)d_in[m.gW2];
    const float* gb2 = (const float*)d_in[m.gb2];
    const float* gW3 = (const float*)d_in[m.gW3];
    const float* gb3 = (const float*)d_in[m.gb3];
    const float* rW1 = (const float*)d_in[m.rW1];
    const float* rb1 = (const float*)d_in[m.rb1];
    const float* rW2 = (const float*)d_in[m.rW2];
    const float* rb2 = (const float*)d_in[m.rb2];
    const float* rW3 = (const float*)d_in[m.rW3];
    const float* rb3 = (const float*)d_in[m.rb3];

    float* out = (float*)d_out;
    int nmlp = (out_size >= 2 * NROWS) ? 2 : 1;

    prep_kernel<<<dim3(NSEG, 2), TPB>>>(z, gW1, gb1, gW2, gb2, gW3, gb3,
                                        rW1, rb1, rW2, rb2, rW3, rb3);
    main_kernel<<<dim3(MAXW, nmlp), TPB>>>(out);
}